// round 6
// baseline (speedup 1.0000x reference)
#include <cuda_runtime.h>
#include <cstdint>

#define N_CELL 200000
#define N_WELL 2000
#define E_CC   1200000
#define E_CW   200000
#define CF     16
#define WF     8
#define H      128
#define OUT    75

// ---------------- device scratch ----------------
__device__ __align__(16) float g_aggx[(size_t)N_CELL * CF];
__device__ int      g_cnt[N_CELL];
__device__ unsigned g_bm[(N_CELL + 31) / 32];

// well-CSR
__device__ int g_wdeg[N_WELL];
__device__ int g_wbase[N_WELL + 1];
__device__ int g_wfill[N_WELL];
__device__ int g_elist[E_CW];

// fused-weight pipeline
// F rows: [0,16) M1 (Un), [16,32) M2 (Vn), 32 v1 (beta_n), 33 v2 (mask),
//         [34,42) M3 (wx), 42 v3 (const)
__device__ float g_T1[43 * H];
__device__ float g_T2[34 * H];
__device__ float g_F[43 * H];

__device__ __forceinline__ void red4(float* p, float a, float b, float c, float d) {
    asm volatile("red.global.add.v4.f32 [%0], {%1,%2,%3,%4};"
                 :: "l"(p), "f"(a), "f"(b), "f"(c), "f"(d) : "memory");
}

// ---------------- zero kernels ----------------
__global__ void k_zero_cell() {
    int i = blockIdx.x * blockDim.x + threadIdx.x;
    if (i < N_CELL * CF / 4) ((float4*)g_aggx)[i] = make_float4(0.f, 0.f, 0.f, 0.f);
    if (i < N_CELL) g_cnt[i] = 0;
    if (i < (N_CELL + 31) / 32) g_bm[i] = 0u;
}
__global__ void k_zero_wd() {
    int i = blockIdx.x * blockDim.x + threadIdx.x;
    if (i < N_WELL) g_wdeg[i] = 0;
}

// ---------------- mark active cells ----------------
__global__ void k_mark(const int* __restrict__ ews) {
    int e = blockIdx.x * blockDim.x + threadIdx.x;
    if (e >= E_CW) return;
    int s = __ldg(&ews[e]);
    atomicOr(&g_bm[s >> 5], 1u << (s & 31));
}

// ---------------- well-CSR build ----------------
__global__ void k_wcount(const int* __restrict__ ewd) {
    int e = blockIdx.x * blockDim.x + threadIdx.x;
    if (e >= E_CW) return;
    atomicAdd(&g_wdeg[__ldg(&ewd[e])], 1);
}

__global__ void __launch_bounds__(1024) k_wscan() {
    __shared__ int sa[1024], sb[1024];
    int t = threadIdx.x;
    int a = (2 * t     < N_WELL) ? g_wdeg[2 * t]     : 0;
    int b = (2 * t + 1 < N_WELL) ? g_wdeg[2 * t + 1] : 0;
    sa[t] = a + b;
    __syncthreads();
    int* bufs[2] = { sa, sb };
    int cur = 0;
    for (int d = 1; d < 1024; d <<= 1) {
        int v = bufs[cur][t] + ((t >= d) ? bufs[cur][t - d] : 0);
        bufs[cur ^ 1][t] = v;
        __syncthreads();
        cur ^= 1;
    }
    int incl = bufs[cur][t];
    int excl = incl - (a + b);
    if (2 * t < N_WELL)     { g_wbase[2 * t]     = excl;     g_wfill[2 * t]     = 0; }
    if (2 * t + 1 < N_WELL) { g_wbase[2 * t + 1] = excl + a; g_wfill[2 * t + 1] = 0; }
    if (t == 1023) g_wbase[N_WELL] = incl;
}

__global__ void k_wfill(const int* __restrict__ ews, const int* __restrict__ ewd) {
    int e = blockIdx.x * blockDim.x + threadIdx.x;
    if (e >= E_CW) return;
    int w = __ldg(&ewd[e]);
    int p = atomicAdd(&g_wfill[w], 1);
    g_elist[g_wbase[w] + p] = __ldg(&ews[e]);
}

// ---------------- fuse-stage body ----------------
__device__ __forceinline__ void stage_row(const float* __restrict__ L,
                                          const float* __restrict__ M,
                                          float* __restrict__ dst,
                                          const float* __restrict__ addv,
                                          float* sL, float* sP)
{
    int tid  = threadIdx.x;
    int h    = tid & (H - 1);
    int half = tid >> 7;
    if (half == 0) sL[h] = __ldg(&L[h]);
    __syncthreads();
    float acc = 0.f;
    int k0 = half * 64;
#pragma unroll 16
    for (int k = 0; k < 64; k++)
        acc += sL[k0 + k] * __ldg(&M[(k0 + k) * H + h]);
    sP[tid] = acc;
    __syncthreads();
    if (half == 0) {
        float v = sP[h] + sP[h + 128];
        if (addv) v += __ldg(&addv[h]);
        dst[h] = v;
    }
}

__global__ void __launch_bounds__(256) k_f1(
    const float* __restrict__ W_cell, const float* __restrict__ b_cell,
    const float* __restrict__ Wl_cc, const float* __restrict__ Wr_cc,
    const float* __restrict__ bl_cc,
    const float* __restrict__ W_well, const float* __restrict__ b_well,
    const float* __restrict__ Wr_cw, const float* __restrict__ bl_cw)
{
    __shared__ float sL[H];
    __shared__ float sP[256];
    int r = blockIdx.x;
    const float* L; const float* M; const float* A = nullptr;
    if (r < 16)      { L = W_cell + r * H;        M = Wl_cc; }
    else if (r < 32) { L = W_cell + (r - 16) * H; M = Wr_cc; }
    else if (r == 32){ L = b_cell;                M = Wl_cc; }
    else if (r == 33){ L = b_cell;                M = Wr_cc; A = bl_cc; }
    else if (r < 42) { L = W_well + (r - 34) * H; M = Wr_cw; }
    else             { L = b_well;                M = Wr_cw; A = bl_cw; }
    stage_row(L, M, g_T1 + r * H, A, sL, sP);
}

__global__ void __launch_bounds__(256) k_f2(const float* __restrict__ Wl_cw)
{
    __shared__ float sL[H];
    __shared__ float sP[256];
    int r = blockIdx.x;
    stage_row(g_T1 + r * H, Wl_cw, g_T2 + r * H, nullptr, sL, sP);
}

__global__ void __launch_bounds__(256) k_f3(const float* __restrict__ Wm1,
                                            const float* __restrict__ bm1)
{
    __shared__ float sL[H];
    __shared__ float sP[256];
    int r = blockIdx.x;
    const float* L = (r < 34) ? (g_T2 + r * H) : (g_T1 + r * H);
    const float* A = (r == 42) ? bm1 : nullptr;
    stage_row(L, Wm1, g_F + r * H, A, sL, sP);
}

// ---------------- K3: scan cell-cell edges (2 edges/thread) ----------------
__global__ void k_cc(const int* __restrict__ ei, const float* __restrict__ x) {
    int t = blockIdx.x * blockDim.x + threadIdx.x;
    if (t >= E_CC / 2) return;
#pragma unroll
    for (int half = 0; half < 2; half++) {
        int e = t + half * (E_CC / 2);
        int d = __ldg(&ei[E_CC + e]);
        if ((g_bm[d >> 5] >> (d & 31)) & 1u) {
            int s = __ldg(&ei[e]);
            const float4* xp = (const float4*)(x + (size_t)s * CF);
            float* ap = g_aggx + (size_t)d * CF;
            float4 v0 = __ldg(xp + 0), v1 = __ldg(xp + 1), v2 = __ldg(xp + 2), v3 = __ldg(xp + 3);
            red4(ap + 0,  v0.x, v0.y, v0.z, v0.w);
            red4(ap + 4,  v1.x, v1.y, v1.z, v1.w);
            red4(ap + 8,  v2.x, v2.y, v2.z, v2.w);
            red4(ap + 12, v3.x, v3.y, v3.z, v3.w);
            atomicAdd(&g_cnt[d], 1);
        }
    }
}

// ---------------- fused well aggregation + head ----------------
// 1 warp per well (phase 1), then 256 threads over 8 wells (phase 2)
__global__ void __launch_bounds__(256) k_wellf(
    const float* __restrict__ x,
    const float* __restrict__ well_x,
    const float* __restrict__ Wm2, const float* __restrict__ bm2,
    float* __restrict__ out)
{
    __shared__ float sU[8][17], sV[8][17];
    __shared__ float sWX[8][8];
    __shared__ float sb1[8], sb2[8];
    __shared__ __align__(16) float sm[H][8];

    int tid = threadIdx.x;
    int warp = tid >> 5, lane = tid & 31;
    int w = blockIdx.x * 8 + warp;
    int base = g_wbase[w];
    int deg  = g_wbase[w + 1] - base;
    int comp = lane & 15, half = lane >> 4;

    float aU0 = 0.f, aV0 = 0.f, aU1 = 0.f, aV1 = 0.f, bt = 0.f;
    int i = half;
    for (; i + 2 < deg; i += 4) {
        int s0 = __ldg(&g_elist[base + i]);
        int s1 = __ldg(&g_elist[base + i + 2]);
        int c0 = g_cnt[s0], c1 = g_cnt[s1];
        float inv0 = (c0 > 0) ? (1.f / (float)c0) : 0.f;
        float inv1 = (c1 > 0) ? (1.f / (float)c1) : 0.f;
        aV0 += __ldg(&x[(size_t)s0 * CF + comp]);
        aU0 += g_aggx[(size_t)s0 * CF + comp] * inv0;
        aV1 += __ldg(&x[(size_t)s1 * CF + comp]);
        aU1 += g_aggx[(size_t)s1 * CF + comp] * inv1;
        if (comp == 0) bt += ((c0 > 0) ? 1.f : 0.f) + ((c1 > 0) ? 1.f : 0.f);
    }
    for (; i < deg; i += 2) {
        int s0 = __ldg(&g_elist[base + i]);
        int c0 = g_cnt[s0];
        float inv0 = (c0 > 0) ? (1.f / (float)c0) : 0.f;
        aV0 += __ldg(&x[(size_t)s0 * CF + comp]);
        aU0 += g_aggx[(size_t)s0 * CF + comp] * inv0;
        if (comp == 0) bt += (c0 > 0) ? 1.f : 0.f;
    }
    float aU = aU0 + aU1, aV = aV0 + aV1;
    aU += __shfl_xor_sync(0xffffffffu, aU, 16);
    aV += __shfl_xor_sync(0xffffffffu, aV, 16);
    bt += __shfl_xor_sync(0xffffffffu, bt, 16);
    float invW = 1.f / fmaxf((float)deg, 1.f);
    if (lane < 16) { sU[warp][lane] = aU * invW; sV[warp][lane] = aV * invW; }
    if (lane == 0) { sb1[warp] = bt * invW; sb2[warp] = (deg > 0) ? 1.f : 0.f; }
    if (lane < WF) sWX[warp][lane] = __ldg(&well_x[w * WF + lane]);
    __syncthreads();

    // phase 2: 2 thread-sets x 128 h-components, 4 wells each
    int h = tid & (H - 1);
    int t0 = (tid >> 7) * 4;
    float acc[4];
    {
        float f1 = g_F[32 * H + h], f2 = g_F[33 * H + h], f3 = g_F[42 * H + h];
#pragma unroll
        for (int q = 0; q < 4; q++) acc[q] = f3 + sb1[t0 + q] * f1 + sb2[t0 + q] * f2;
    }
#pragma unroll
    for (int j = 0; j < CF; j++) {
        float m1 = g_F[j * H + h];
        float m2 = g_F[(16 + j) * H + h];
#pragma unroll
        for (int q = 0; q < 4; q++) acc[q] += sU[t0 + q][j] * m1 + sV[t0 + q][j] * m2;
    }
#pragma unroll
    for (int j = 0; j < WF; j++) {
        float m3 = g_F[(34 + j) * H + h];
#pragma unroll
        for (int q = 0; q < 4; q++) acc[q] += sWX[t0 + q][j] * m3;
    }
#pragma unroll
    for (int q = 0; q < 4; q++) sm[h][t0 + q] = fmaxf(acc[q], 0.f);
    __syncthreads();

    if (h < OUT) {
        float o[4];
        float bv = __ldg(&bm2[h]);
#pragma unroll
        for (int q = 0; q < 4; q++) o[q] = bv;
#pragma unroll 4
        for (int k = 0; k < H; k++) {
            float wm = __ldg(&Wm2[k * OUT + h]);
            float4 p = *(const float4*)&sm[k][t0];
            o[0] += p.x * wm; o[1] += p.y * wm;
            o[2] += p.z * wm; o[3] += p.w * wm;
        }
#pragma unroll
        for (int q = 0; q < 4; q++)
            out[(blockIdx.x * 8 + t0 + q) * OUT + h] = o[q];
    }
}

// ---------------- launch (fork-join over 2 streams, capture-safe) ---------
static cudaStream_t s1;
static cudaEvent_t evRoot, evW;
static bool g_host_init = false;

extern "C" void kernel_launch(void* const* d_in, const int* in_sizes, int n_in,
                              void* d_out, int out_size)
{
    if (!g_host_init) {
        cudaStreamCreateWithFlags(&s1, cudaStreamNonBlocking);
        cudaEventCreateWithFlags(&evRoot, cudaEventDisableTiming);
        cudaEventCreateWithFlags(&evW, cudaEventDisableTiming);
        g_host_init = true;
    }

    const float* cell_x  = (const float*)d_in[0];
    const float* well_x  = (const float*)d_in[1];
    const int*   ei_cell = (const int*)  d_in[2];
    const int*   ews     = (const int*)  d_in[3];
    const int*   ewd     = (const int*)  d_in[4];
    const float* W_cell  = (const float*)d_in[5];
    const float* b_cell  = (const float*)d_in[6];
    const float* W_well  = (const float*)d_in[7];
    const float* b_well  = (const float*)d_in[8];
    const float* Wl_cc   = (const float*)d_in[9];
    const float* bl_cc   = (const float*)d_in[10];
    const float* Wr_cc   = (const float*)d_in[11];
    const float* Wl_cw   = (const float*)d_in[12];
    const float* bl_cw   = (const float*)d_in[13];
    const float* Wr_cw   = (const float*)d_in[14];
    const float* W_m1    = (const float*)d_in[15];
    const float* b_m1    = (const float*)d_in[16];
    const float* W_m2    = (const float*)d_in[17];
    const float* b_m2    = (const float*)d_in[18];
    float* out = (float*)d_out;

    // fork
    cudaEventRecord(evRoot, 0);
    cudaStreamWaitEvent(s1, evRoot, 0);

    // side stream: well-CSR build + fuse chain (independent of k_cc)
    k_zero_wd<<<(N_WELL + 255) / 256, 256, 0, s1>>>();
    k_wcount<<<(E_CW + 255) / 256, 256, 0, s1>>>(ewd);
    k_wscan<<<1, 1024, 0, s1>>>();
    k_wfill<<<(E_CW + 255) / 256, 256, 0, s1>>>(ews, ewd);
    k_f1<<<43, 256, 0, s1>>>(W_cell, b_cell, Wl_cc, Wr_cc, bl_cc, W_well, b_well, Wr_cw, bl_cw);
    k_f2<<<34, 256, 0, s1>>>(Wl_cw);
    k_f3<<<43, 256, 0, s1>>>(W_m1, b_m1);
    cudaEventRecord(evW, s1);

    // main stream: critical path
    k_zero_cell<<<(N_CELL * CF / 4 + 255) / 256, 256>>>();
    k_mark<<<(E_CW + 255) / 256, 256>>>(ews);
    k_cc<<<(E_CC / 2 + 255) / 256, 256>>>(ei_cell, cell_x);
    cudaStreamWaitEvent(0, evW, 0);   // join
    k_wellf<<<N_WELL / 8, 256>>>(cell_x, well_x, W_m2, b_m2, out);
}

// round 7
// speedup vs baseline: 1.9194x; 1.9194x over previous
#include <cuda_runtime.h>
#include <cstdint>

#define N_CELL 200000
#define N_WELL 2000
#define E_CC   1200000
#define E_CW   200000
#define CF     16
#define WF     8
#define H      128
#define OUT    75
#define WPB    8
#define R      16

// ---------------- device scratch ----------------
__device__ __align__(16) float g_aggx[(size_t)N_CELL * CF];
__device__ int      g_cnt[N_CELL];
__device__ unsigned g_bm[(N_CELL + 31) / 32];
__device__ __align__(16) float g_Ur[(size_t)R * N_WELL * CF];
__device__ __align__(16) float g_Vr[(size_t)R * N_WELL * CF];
__device__ __align__(16) float g_meta[(size_t)R * N_WELL * 4];   // {beta, count, 0, 0}

// fused-weight pipeline
// F rows: [0,16) M1 (Un), [16,32) M2 (Vn), 32 v1 (beta_n), 33 v2 (mask),
//         [34,42) M3 (wx), 42 v3 (const)
__device__ float g_T1[43 * H];
__device__ float g_T2[34 * H];
__device__ float g_F[43 * H];

__device__ __forceinline__ void red4(float* p, float a, float b, float c, float d) {
    asm volatile("red.global.add.v4.f32 [%0], {%1,%2,%3,%4};"
                 :: "l"(p), "f"(a), "f"(b), "f"(c), "f"(d) : "memory");
}

// ---------------- zero kernels ----------------
__global__ void k_zero_bm() {             // 25 KB only
    int i = blockIdx.x * blockDim.x + threadIdx.x;
    if (i < (N_CELL + 31) / 32) g_bm[i] = 0u;
}
__global__ void k_zero_well() {
    int i = blockIdx.x * blockDim.x + threadIdx.x;
    if (i < R * N_WELL * CF / 4) {
        ((float4*)g_Ur)[i] = make_float4(0.f, 0.f, 0.f, 0.f);
        ((float4*)g_Vr)[i] = make_float4(0.f, 0.f, 0.f, 0.f);
    }
    if (i < R * N_WELL) ((float4*)g_meta)[i] = make_float4(0.f, 0.f, 0.f, 0.f);
}

// ---------------- mark active cells + zero their accumulators ----------------
__global__ void k_mark(const int* __restrict__ ews) {
    int e = blockIdx.x * blockDim.x + threadIdx.x;
    if (e >= E_CW) return;
    int s = __ldg(&ews[e]);
    unsigned old = atomicOr(&g_bm[s >> 5], 1u << (s & 31));
    if (!((old >> (s & 31)) & 1u)) {      // first marker zeroes (races write 0 only)
        float4 z = make_float4(0.f, 0.f, 0.f, 0.f);
        float4* ap = (float4*)(g_aggx + (size_t)s * CF);
        ap[0] = z; ap[1] = z; ap[2] = z; ap[3] = z;
        g_cnt[s] = 0;
    }
}

// ---------------- fuse-stage body ----------------
__device__ __forceinline__ void stage_row(const float* __restrict__ L,
                                          const float* __restrict__ M,
                                          float* __restrict__ dst,
                                          const float* __restrict__ addv,
                                          float* sL, float* sP)
{
    int tid  = threadIdx.x;
    int h    = tid & (H - 1);
    int half = tid >> 7;
    if (half == 0) sL[h] = __ldg(&L[h]);
    __syncthreads();
    float acc = 0.f;
    int k0 = half * 64;
#pragma unroll 16
    for (int k = 0; k < 64; k++)
        acc += sL[k0 + k] * __ldg(&M[(k0 + k) * H + h]);
    sP[tid] = acc;
    __syncthreads();
    if (half == 0) {
        float v = sP[h] + sP[h + 128];
        if (addv) v += __ldg(&addv[h]);
        dst[h] = v;
    }
}

__global__ void __launch_bounds__(256) k_f1(
    const float* __restrict__ W_cell, const float* __restrict__ b_cell,
    const float* __restrict__ Wl_cc, const float* __restrict__ Wr_cc,
    const float* __restrict__ bl_cc,
    const float* __restrict__ W_well, const float* __restrict__ b_well,
    const float* __restrict__ Wr_cw, const float* __restrict__ bl_cw)
{
    __shared__ float sL[H];
    __shared__ float sP[256];
    int r = blockIdx.x;
    const float* L; const float* M; const float* A = nullptr;
    if (r < 16)      { L = W_cell + r * H;        M = Wl_cc; }
    else if (r < 32) { L = W_cell + (r - 16) * H; M = Wr_cc; }
    else if (r == 32){ L = b_cell;                M = Wl_cc; }
    else if (r == 33){ L = b_cell;                M = Wr_cc; A = bl_cc; }
    else if (r < 42) { L = W_well + (r - 34) * H; M = Wr_cw; }
    else             { L = b_well;                M = Wr_cw; A = bl_cw; }
    stage_row(L, M, g_T1 + r * H, A, sL, sP);
}

__global__ void __launch_bounds__(256) k_f2(const float* __restrict__ Wl_cw)
{
    __shared__ float sL[H];
    __shared__ float sP[256];
    int r = blockIdx.x;
    stage_row(g_T1 + r * H, Wl_cw, g_T2 + r * H, nullptr, sL, sP);
}

__global__ void __launch_bounds__(256) k_f3(const float* __restrict__ Wm1,
                                            const float* __restrict__ bm1)
{
    __shared__ float sL[H];
    __shared__ float sP[256];
    int r = blockIdx.x;
    const float* L = (r < 34) ? (g_T2 + r * H) : (g_T1 + r * H);
    const float* A = (r == 42) ? bm1 : nullptr;
    stage_row(L, Wm1, g_F + r * H, A, sL, sP);
}

// ---------------- K3: scan cell-cell edges (2 edges/thread) ----------------
__global__ void k_cc(const int* __restrict__ ei, const float* __restrict__ x) {
    int t = blockIdx.x * blockDim.x + threadIdx.x;
    if (t >= E_CC / 2) return;
#pragma unroll
    for (int half = 0; half < 2; half++) {
        int e = t + half * (E_CC / 2);
        int d = __ldg(&ei[E_CC + e]);
        if ((g_bm[d >> 5] >> (d & 31)) & 1u) {
            int s = __ldg(&ei[e]);
            const float4* xp = (const float4*)(x + (size_t)s * CF);
            float* ap = g_aggx + (size_t)d * CF;
            float4 v0 = __ldg(xp + 0), v1 = __ldg(xp + 1), v2 = __ldg(xp + 2), v3 = __ldg(xp + 3);
            red4(ap + 0,  v0.x, v0.y, v0.z, v0.w);
            red4(ap + 4,  v1.x, v1.y, v1.z, v1.w);
            red4(ap + 8,  v2.x, v2.y, v2.z, v2.w);
            red4(ap + 12, v3.x, v3.y, v3.z, v3.w);
            atomicAdd(&g_cnt[d], 1);
        }
    }
}

// ---------------- side half: V-sum + edge count (independent of k_cc) ------
__global__ void k_cwV(const int* __restrict__ ews, const int* __restrict__ ewd,
                      const float* __restrict__ x) {
    int e = blockIdx.x * blockDim.x + threadIdx.x;
    if (e >= E_CW) return;
    int rep = blockIdx.x & (R - 1);
    int s = __ldg(&ews[e]);
    int w = __ldg(&ewd[e]);
    const float4* xp = (const float4*)(x + (size_t)s * CF);
    float* V = g_Vr + ((size_t)rep * N_WELL + w) * CF;
    float4 b0 = __ldg(xp + 0), b1 = __ldg(xp + 1), b2 = __ldg(xp + 2), b3 = __ldg(xp + 3);
    red4(V + 0,  b0.x, b0.y, b0.z, b0.w);
    red4(V + 4,  b1.x, b1.y, b1.z, b1.w);
    red4(V + 8,  b2.x, b2.y, b2.z, b2.w);
    red4(V + 12, b3.x, b3.y, b3.z, b3.w);
    red4(g_meta + ((size_t)rep * N_WELL + w) * 4, 0.f, 1.f, 0.f, 0.f);
}

// ---------------- critical half: U-sum + beta (needs g_cnt from k_cc) ------
__global__ void k_cwU(const int* __restrict__ ews, const int* __restrict__ ewd) {
    int e = blockIdx.x * blockDim.x + threadIdx.x;
    if (e >= E_CW) return;
    int rep = blockIdx.x & (R - 1);
    int s = __ldg(&ews[e]);
    int w = __ldg(&ewd[e]);
    int c = g_cnt[s];
    float inv = (c > 0) ? (1.f / (float)c) : 0.f;
    const float4* ap = (const float4*)(g_aggx + (size_t)s * CF);
    float* U = g_Ur + ((size_t)rep * N_WELL + w) * CF;
    float4 a0 = ap[0], a1 = ap[1], a2 = ap[2], a3 = ap[3];
    red4(U + 0,  a0.x * inv, a0.y * inv, a0.z * inv, a0.w * inv);
    red4(U + 4,  a1.x * inv, a1.y * inv, a1.z * inv, a1.w * inv);
    red4(U + 8,  a2.x * inv, a2.y * inv, a2.z * inv, a2.w * inv);
    red4(U + 12, a3.x * inv, a3.y * inv, a3.z * inv, a3.w * inv);
    red4(g_meta + ((size_t)rep * N_WELL + w) * 4, (c > 0) ? 1.f : 0.f, 0.f, 0.f, 0.f);
}

// ---------------- K6: per-well head ----------------
__global__ void __launch_bounds__(H) k_well(
    const float* __restrict__ well_x,
    const float* __restrict__ Wm2, const float* __restrict__ bm2,
    float* __restrict__ out)
{
    __shared__ __align__(16) float sm[H][WPB];
    __shared__ float sUn[WPB][CF], sVn[WPB][CF], sWX[WPB][WF];
    __shared__ float sb1[WPB], sb2[WPB], sinv[WPB];

    int h  = threadIdx.x;
    int w0 = blockIdx.x * WPB;

    if (h < WPB) {
        float beta = 0.f, cw = 0.f;
#pragma unroll
        for (int r = 0; r < R; r++) {
            const float* mp = g_meta + ((size_t)r * N_WELL + (w0 + h)) * 4;
            beta += mp[0];
            cw   += mp[1];
        }
        float inv = 1.f / fmaxf(cw, 1.f);
        sinv[h] = inv;
        sb1[h]  = beta * inv;
        sb2[h]  = (cw > 0.5f) ? 1.f : 0.f;
    }
    __syncthreads();
    {
        int t = h >> 4, j = h & 15;
        float su = 0.f, svv = 0.f;
#pragma unroll
        for (int r = 0; r < R; r++) {
            size_t off = ((size_t)r * N_WELL + (w0 + t)) * CF + j;
            su  += g_Ur[off];
            svv += g_Vr[off];
        }
        sUn[t][j] = su * sinv[t];
        sVn[t][j] = svv * sinv[t];
    }
    if (h < WPB * WF) {
        int t = h >> 3, j = h & 7;
        sWX[t][j] = __ldg(&well_x[(w0 + t) * WF + j]);
    }
    __syncthreads();

    float acc[WPB];
    {
        float f1 = g_F[32 * H + h], f2 = g_F[33 * H + h], f3 = g_F[42 * H + h];
#pragma unroll
        for (int t = 0; t < WPB; t++) acc[t] = f3 + sb1[t] * f1 + sb2[t] * f2;
    }
#pragma unroll
    for (int j = 0; j < CF; j++) {
        float m1 = g_F[j * H + h];
        float m2 = g_F[(16 + j) * H + h];
#pragma unroll
        for (int t = 0; t < WPB; t++) acc[t] += sUn[t][j] * m1 + sVn[t][j] * m2;
    }
#pragma unroll
    for (int j = 0; j < WF; j++) {
        float m3 = g_F[(34 + j) * H + h];
#pragma unroll
        for (int t = 0; t < WPB; t++) acc[t] += sWX[t][j] * m3;
    }
#pragma unroll
    for (int t = 0; t < WPB; t++) sm[h][t] = fmaxf(acc[t], 0.f);
    __syncthreads();

    if (h < OUT) {
        float o[WPB];
        float bv = __ldg(&bm2[h]);
#pragma unroll
        for (int t = 0; t < WPB; t++) o[t] = bv;
#pragma unroll 4
        for (int k = 0; k < H; k++) {
            float wm = __ldg(&Wm2[k * OUT + h]);
            float4 p0 = *(const float4*)&sm[k][0];
            float4 p1 = *(const float4*)&sm[k][4];
            o[0] += p0.x * wm;  o[1] += p0.y * wm;
            o[2] += p0.z * wm;  o[3] += p0.w * wm;
            o[4] += p1.x * wm;  o[5] += p1.y * wm;
            o[6] += p1.z * wm;  o[7] += p1.w * wm;
        }
#pragma unroll
        for (int t = 0; t < WPB; t++) out[(w0 + t) * OUT + h] = o[t];
    }
}

// ---------------- launch (fork-join over 2 streams, capture-safe) ---------
static cudaStream_t s1;
static cudaEvent_t evRoot, evZ, evV;
static bool g_host_init = false;

extern "C" void kernel_launch(void* const* d_in, const int* in_sizes, int n_in,
                              void* d_out, int out_size)
{
    if (!g_host_init) {
        cudaStreamCreateWithFlags(&s1, cudaStreamNonBlocking);
        cudaEventCreateWithFlags(&evRoot, cudaEventDisableTiming);
        cudaEventCreateWithFlags(&evZ, cudaEventDisableTiming);
        cudaEventCreateWithFlags(&evV, cudaEventDisableTiming);
        g_host_init = true;
    }

    const float* cell_x  = (const float*)d_in[0];
    const float* well_x  = (const float*)d_in[1];
    const int*   ei_cell = (const int*)  d_in[2];
    const int*   ews     = (const int*)  d_in[3];
    const int*   ewd     = (const int*)  d_in[4];
    const float* W_cell  = (const float*)d_in[5];
    const float* b_cell  = (const float*)d_in[6];
    const float* W_well  = (const float*)d_in[7];
    const float* b_well  = (const float*)d_in[8];
    const float* Wl_cc   = (const float*)d_in[9];
    const float* bl_cc   = (const float*)d_in[10];
    const float* Wr_cc   = (const float*)d_in[11];
    const float* Wl_cw   = (const float*)d_in[12];
    const float* bl_cw   = (const float*)d_in[13];
    const float* Wr_cw   = (const float*)d_in[14];
    const float* W_m1    = (const float*)d_in[15];
    const float* b_m1    = (const float*)d_in[16];
    const float* W_m2    = (const float*)d_in[17];
    const float* b_m2    = (const float*)d_in[18];
    float* out = (float*)d_out;

    // fork
    cudaEventRecord(evRoot, 0);
    cudaStreamWaitEvent(s1, evRoot, 0);

    // side stream: zero well accumulators, fuse chain, V-half of cw
    k_zero_well<<<(R * N_WELL * CF / 4 + 255) / 256, 256, 0, s1>>>();
    k_f1<<<43, 256, 0, s1>>>(W_cell, b_cell, Wl_cc, Wr_cc, bl_cc, W_well, b_well, Wr_cw, bl_cw);
    k_f2<<<34, 256, 0, s1>>>(Wl_cw);
    k_f3<<<43, 256, 0, s1>>>(W_m1, b_m1);
    cudaEventRecord(evZ, s1);                 // zero_well done (U reds may start)
    k_cwV<<<(E_CW + 255) / 256, 256, 0, s1>>>(ews, ewd, cell_x);
    cudaEventRecord(evV, s1);

    // main stream: critical path
    k_zero_bm<<<((N_CELL + 31) / 32 + 255) / 256, 256>>>();
    k_mark<<<(E_CW + 255) / 256, 256>>>(ews);
    k_cc<<<(E_CC / 2 + 255) / 256, 256>>>(ei_cell, cell_x);
    cudaStreamWaitEvent(0, evZ, 0);
    k_cwU<<<(E_CW + 255) / 256, 256>>>(ews, ewd);
    cudaStreamWaitEvent(0, evV, 0);
    k_well<<<N_WELL / WPB, H>>>(well_x, W_m2, b_m2, out);
}